// round 3
// baseline (speedup 1.0000x reference)
#include <cuda_runtime.h>
#include <math.h>
#include <stdint.h>

// Problem constants
#define TOK   131072        // B*D*H*W = 2*4*128*128
#define CCH   256
#define NH    8
#define HD    32
#define HID_N 1024

// ---------------------------------------------------------------------------
// Scratch buffers (__device__ globals — no allocations allowed)
// ---------------------------------------------------------------------------
__device__ float g_h  [TOK * CCH];     // LN output / reused
__device__ float g_qkv[TOK * 3 * CCH]; // qkv projections (reused for both attns)
__device__ float g_ctx[TOK * CCH];     // attention context (pre-proj)
__device__ float g_a  [TOK * CCH];     // spatial attention output
__device__ float g_hid[TOK * HID_N];   // MLP hidden

// ---------------------------------------------------------------------------
// LayerNorm: one warp per token (C=256)
// ---------------------------------------------------------------------------
__global__ void __launch_bounds__(256) ln_kernel(
    const float* __restrict__ x, const float* __restrict__ gamma,
    const float* __restrict__ beta, float* __restrict__ out)
{
    int warp = threadIdx.x >> 5, lane = threadIdx.x & 31;
    int token = blockIdx.x * 8 + warp;
    const float* xp = x + token * CCH;
    float4 x0 = *(const float4*)(xp + lane * 4);
    float4 x1 = *(const float4*)(xp + 128 + lane * 4);
    float s  = x0.x + x0.y + x0.z + x0.w + x1.x + x1.y + x1.z + x1.w;
    float s2 = x0.x*x0.x + x0.y*x0.y + x0.z*x0.z + x0.w*x0.w
             + x1.x*x1.x + x1.y*x1.y + x1.z*x1.z + x1.w*x1.w;
    #pragma unroll
    for (int o = 16; o > 0; o >>= 1) {
        s  += __shfl_xor_sync(0xffffffffu, s,  o);
        s2 += __shfl_xor_sync(0xffffffffu, s2, o);
    }
    float mu  = s * (1.0f / CCH);
    float var = s2 * (1.0f / CCH) - mu * mu;
    float rstd = rsqrtf(var + 1e-5f);
    float4 g0 = *(const float4*)(gamma + lane * 4);
    float4 g1 = *(const float4*)(gamma + 128 + lane * 4);
    float4 b0 = *(const float4*)(beta + lane * 4);
    float4 b1 = *(const float4*)(beta + 128 + lane * 4);
    float* op = out + token * CCH;
    float4 r0, r1;
    r0.x = (x0.x - mu) * rstd * g0.x + b0.x;
    r0.y = (x0.y - mu) * rstd * g0.y + b0.y;
    r0.z = (x0.z - mu) * rstd * g0.z + b0.z;
    r0.w = (x0.w - mu) * rstd * g0.w + b0.w;
    r1.x = (x1.x - mu) * rstd * g1.x + b1.x;
    r1.y = (x1.y - mu) * rstd * g1.y + b1.y;
    r1.z = (x1.z - mu) * rstd * g1.z + b1.z;
    r1.w = (x1.w - mu) * rstd * g1.w + b1.w;
    *(float4*)(op + lane * 4) = r0;
    *(float4*)(op + 128 + lane * 4) = r1;
}

// ---------------------------------------------------------------------------
// tf32 helpers
// ---------------------------------------------------------------------------
__device__ __forceinline__ uint32_t f2tf32(float f) {
    uint32_t u;
    asm("cvt.rna.tf32.f32 %0, %1;" : "=r"(u) : "f"(f));
    return u;
}

#define MMA_TF32(d, a, b) \
    asm volatile( \
        "mma.sync.aligned.m16n8k8.row.col.f32.tf32.tf32.f32 " \
        "{%0,%1,%2,%3}, {%4,%5,%6,%7}, {%8,%9}, {%0,%1,%2,%3};\n" \
        : "+f"((d)[0]), "+f"((d)[1]), "+f"((d)[2]), "+f"((d)[3]) \
        : "r"((a)[0]), "r"((a)[1]), "r"((a)[2]), "r"((a)[3]), \
          "r"((b)[0]), "r"((b)[1]))

// ---------------------------------------------------------------------------
// tf32 tensor-core GEMM: out[M,N] = A[M,K] @ W[N,K]^T + bias, with epilogue
// EPI: 0 = bias, 1 = bias+GELU(exact), 2 = bias + aux residual add
// BM=BN=128, BK=32, 256 threads = 8 warps (2 along M x 4 along N),
// warp tile 64x32 = 4 m-tiles(16) x 4 n-tiles(8), mma.m16n8k8.tf32
// ---------------------------------------------------------------------------
template <int EPI>
__global__ void __launch_bounds__(256) gemm_tc_kernel(
    const float* __restrict__ A, const float* __restrict__ W,
    const float* __restrict__ bias, const float* __restrict__ aux,
    float* __restrict__ out, int M, int N, int K)
{
    constexpr int BM = 128, BN = 128, BK = 32;
    __shared__ float As[BM][BK + 4];   // [m][k], pad 4 -> conflict-free frags
    __shared__ float Bs[BN][BK + 4];   // [n][k]

    const int tid  = threadIdx.x;
    const int wid  = tid >> 5, lane = tid & 31;
    const int g    = lane >> 2, tg = lane & 3;
    const int wm   = (wid & 1) * 64;        // warp row base in tile
    const int wn   = (wid >> 1) * 32;       // warp col base in tile
    const int bm   = blockIdx.y * BM, bn = blockIdx.x * BN;

    // global load mapping: 32 rows per pass, 8 float4 per row
    const int lr = tid >> 3;                // 0..31
    const int lc = (tid & 7) * 4;           // 0,4,...,28
    const float* Ag = A + (size_t)(bm + lr) * K + lc;
    const float* Wg = W + (size_t)(bn + lr) * K + lc;

    float acc[4][4][4];
    #pragma unroll
    for (int mt = 0; mt < 4; mt++)
        #pragma unroll
        for (int nt = 0; nt < 4; nt++)
            #pragma unroll
            for (int c = 0; c < 4; c++) acc[mt][nt][c] = 0.0f;

    float4 pa[4], pb[4];
    #pragma unroll
    for (int i = 0; i < 4; i++) {
        pa[i] = *(const float4*)(Ag + (size_t)i * 32 * K);
        pb[i] = *(const float4*)(Wg + (size_t)i * 32 * K);
    }

    for (int k0 = 0; k0 < K; k0 += BK) {
        // stage current tiles into smem (tf32-rounded bit patterns)
        #pragma unroll
        for (int i = 0; i < 4; i++) {
            float4 a = pa[i], b = pb[i];
            uint4 au = { f2tf32(a.x), f2tf32(a.y), f2tf32(a.z), f2tf32(a.w) };
            uint4 bu = { f2tf32(b.x), f2tf32(b.y), f2tf32(b.z), f2tf32(b.w) };
            *(uint4*)&As[lr + i * 32][lc] = au;
            *(uint4*)&Bs[lr + i * 32][lc] = bu;
        }
        __syncthreads();

        // prefetch next tiles
        if (k0 + BK < K) {
            #pragma unroll
            for (int i = 0; i < 4; i++) {
                pa[i] = *(const float4*)(Ag + (size_t)i * 32 * K + k0 + BK);
                pb[i] = *(const float4*)(Wg + (size_t)i * 32 * K + k0 + BK);
            }
        }

        // compute: 4 k-steps of 8
        #pragma unroll
        for (int ks = 0; ks < 4; ks++) {
            uint32_t af[4][4], bf[4][2];
            #pragma unroll
            for (int mt = 0; mt < 4; mt++) {
                int r0 = wm + mt * 16 + g;
                af[mt][0] = __float_as_uint(As[r0    ][ks * 8 + tg]);
                af[mt][1] = __float_as_uint(As[r0 + 8][ks * 8 + tg]);
                af[mt][2] = __float_as_uint(As[r0    ][ks * 8 + tg + 4]);
                af[mt][3] = __float_as_uint(As[r0 + 8][ks * 8 + tg + 4]);
            }
            #pragma unroll
            for (int nt = 0; nt < 4; nt++) {
                int c0 = wn + nt * 8 + g;
                bf[nt][0] = __float_as_uint(Bs[c0][ks * 8 + tg]);
                bf[nt][1] = __float_as_uint(Bs[c0][ks * 8 + tg + 4]);
            }
            #pragma unroll
            for (int mt = 0; mt < 4; mt++)
                #pragma unroll
                for (int nt = 0; nt < 4; nt++)
                    MMA_TF32(acc[mt][nt], af[mt], bf[nt]);
        }
        __syncthreads();
    }

    // epilogue
    #pragma unroll
    for (int mt = 0; mt < 4; mt++) {
        int row0 = bm + wm + mt * 16 + g;
        #pragma unroll
        for (int nt = 0; nt < 4; nt++) {
            int col = bn + wn + nt * 8 + tg * 2;
            float bv0 = bias[col], bv1 = bias[col + 1];
            float v00 = acc[mt][nt][0] + bv0, v01 = acc[mt][nt][1] + bv1;
            float v10 = acc[mt][nt][2] + bv0, v11 = acc[mt][nt][3] + bv1;
            if (EPI == 1) {
                v00 = 0.5f * v00 * (1.0f + erff(v00 * 0.70710678118654752f));
                v01 = 0.5f * v01 * (1.0f + erff(v01 * 0.70710678118654752f));
                v10 = 0.5f * v10 * (1.0f + erff(v10 * 0.70710678118654752f));
                v11 = 0.5f * v11 * (1.0f + erff(v11 * 0.70710678118654752f));
            }
            if (EPI == 2) {
                float2 a0 = *(const float2*)(aux + (size_t)row0 * N + col);
                float2 a1 = *(const float2*)(aux + (size_t)(row0 + 8) * N + col);
                v00 += a0.x; v01 += a0.y; v10 += a1.x; v11 += a1.y;
            }
            float2 r0 = { v00, v01 }, r1 = { v10, v11 };
            *(float2*)(out + (size_t)row0 * N + col) = r0;
            *(float2*)(out + (size_t)(row0 + 8) * N + col) = r1;
        }
    }
}

// ---------------------------------------------------------------------------
// Spatial shifted-window attention (window 1x8x8, N=64, shift (0,4,4))
// One block per window (2048 blocks), looping over 8 heads.
// ---------------------------------------------------------------------------
__global__ void __launch_bounds__(256) spat_attn_kernel(
    const float* __restrict__ qkv, const float* __restrict__ table,
    const float* __restrict__ mask, float* __restrict__ ctx)
{
    __shared__ float qs[64][33], ks[64][33], vs[64][33];
    __shared__ float ss[64][65];
    __shared__ int tix[64];
    const int tid = threadIdx.x;
    const int bw = blockIdx.x;
    const int b = bw >> 10, wi = bw & 1023;          // wi = (dwin*16+hwin)*16+wwin
    const int dwin = wi >> 8, hwin = (wi >> 4) & 15, wwin = wi & 15;
    const float rsc = 0.17677669529663687f;          // 1/sqrt(32)

    if (tid < 64) {
        int yy = tid >> 3, xx = tid & 7;
        int h = hwin * 8 + yy, w = wwin * 8 + xx;
        int ho = (h + 4) & 127, wo = (w + 4) & 127;   // undo roll(-shift)
        tix[tid] = ((b * 4 + dwin) * 128 + ho) * 128 + wo;
    }
    __syncthreads();
    const float* maskw = mask + wi * 4096;

    for (int head = 0; head < NH; head++) {
        for (int idx = tid; idx < 2048; idx += 256) {
            int r = idx >> 5, c = idx & 31;
            const float* base = qkv + (size_t)tix[r] * 768 + head * HD + c;
            qs[r][c] = base[0] * rsc;
            ks[r][c] = base[256];
            vs[r][c] = base[512];
        }
        __syncthreads();
        for (int idx = tid; idx < 4096; idx += 256) {
            int i = idx >> 6, j = idx & 63;
            float s = 0.0f;
            #pragma unroll
            for (int c = 0; c < 32; c++) s += qs[i][c] * ks[j][c];
            int yi = i >> 3, xi = i & 7, yj = j >> 3, xj = j & 7;
            int rp = (yi - yj + 7) * 15 + (xi - xj + 7);
            s += table[rp * NH + head] + maskw[idx];
            ss[i][j] = s;
        }
        __syncthreads();
        {   // softmax, 4 threads per row
            int r = tid >> 2, part = tid & 3;
            float m = -1e30f;
            #pragma unroll
            for (int j = 0; j < 16; j++) m = fmaxf(m, ss[r][part * 16 + j]);
            m = fmaxf(m, __shfl_xor_sync(0xffffffffu, m, 1));
            m = fmaxf(m, __shfl_xor_sync(0xffffffffu, m, 2));
            float sum = 0.0f;
            #pragma unroll
            for (int j = 0; j < 16; j++) {
                float e = __expf(ss[r][part * 16 + j] - m);
                ss[r][part * 16 + j] = e;
                sum += e;
            }
            sum += __shfl_xor_sync(0xffffffffu, sum, 1);
            sum += __shfl_xor_sync(0xffffffffu, sum, 2);
            float inv = 1.0f / sum;
            #pragma unroll
            for (int j = 0; j < 16; j++) ss[r][part * 16 + j] *= inv;
        }
        __syncthreads();
        for (int idx = tid; idx < 2048; idx += 256) {
            int i = idx >> 5, c = idx & 31;
            float o = 0.0f;
            #pragma unroll
            for (int j = 0; j < 64; j++) o += ss[i][j] * vs[j][c];
            ctx[(size_t)tix[i] * CCH + head * HD + c] = o;
        }
        __syncthreads();
    }
}

// ---------------------------------------------------------------------------
// Temporal point attention (window 4x1x1, N=4). One block per (b,h,w).
// ---------------------------------------------------------------------------
__global__ void __launch_bounds__(128) temp_attn_kernel(
    const float* __restrict__ qkv, const float* __restrict__ table,
    float* __restrict__ ctx)
{
    __shared__ float qs[4][256], ks[4][256], vs[4][256];
    __shared__ float ps[NH][4][4];
    const int tid = threadIdx.x;
    const int wt = blockIdx.x;
    const int b = wt >> 14, hw = wt & 16383;
    const int base0 = b * 4 * 16384 + hw;   // token index of depth 0

    for (int idx = tid; idx < 1024; idx += 128) {
        int d = idx >> 8, c = idx & 255;
        const float* p = qkv + (size_t)(base0 + d * 16384) * 768 + c;
        qs[d][c] = p[0] * 0.17677669529663687f;
        ks[d][c] = p[256];
        vs[d][c] = p[512];
    }
    __syncthreads();
    {
        int head = tid >> 4, i = (tid >> 2) & 3, j = tid & 3;
        float s = 0.0f;
        #pragma unroll
        for (int c = 0; c < 32; c++) s += qs[i][head * HD + c] * ks[j][head * HD + c];
        s += table[(i - j + 3) * NH + head];
        ps[head][i][j] = s;
    }
    __syncthreads();
    if (tid < 32) {
        int head = tid >> 2, i = tid & 3;
        float a0 = ps[head][i][0], a1 = ps[head][i][1];
        float a2 = ps[head][i][2], a3 = ps[head][i][3];
        float m = fmaxf(fmaxf(a0, a1), fmaxf(a2, a3));
        float e0 = __expf(a0 - m), e1 = __expf(a1 - m);
        float e2 = __expf(a2 - m), e3 = __expf(a3 - m);
        float inv = 1.0f / (e0 + e1 + e2 + e3);
        ps[head][i][0] = e0 * inv; ps[head][i][1] = e1 * inv;
        ps[head][i][2] = e2 * inv; ps[head][i][3] = e3 * inv;
    }
    __syncthreads();
    for (int idx = tid; idx < 1024; idx += 128) {
        int i = idx >> 8, c = idx & 255;
        int head = c >> 5;
        float o = ps[head][i][0] * vs[0][c] + ps[head][i][1] * vs[1][c]
                + ps[head][i][2] * vs[2][c] + ps[head][i][3] * vs[3][c];
        ctx[(size_t)(base0 + i * 16384) * CCH + c] = o;
    }
}

// ---------------------------------------------------------------------------
// Host launch
// ---------------------------------------------------------------------------
extern "C" void kernel_launch(void* const* d_in, const int* in_sizes, int n_in,
                              void* d_out, int out_size)
{
    const float* x       = (const float*)d_in[0];
    const float* maskm   = (const float*)d_in[1];
    const float* n1g     = (const float*)d_in[2];
    const float* n1b     = (const float*)d_in[3];
    const float* d_qkv_w = (const float*)d_in[4];
    const float* d_qkv_b = (const float*)d_in[5];
    const float* d_prj_w = (const float*)d_in[6];
    const float* d_prj_b = (const float*)d_in[7];
    const float* d_tab   = (const float*)d_in[8];
    const float* p_qkv_w = (const float*)d_in[9];
    const float* p_qkv_b = (const float*)d_in[10];
    const float* p_prj_w = (const float*)d_in[11];
    const float* p_prj_b = (const float*)d_in[12];
    const float* p_tab   = (const float*)d_in[13];
    const float* n2g     = (const float*)d_in[14];
    const float* n2b     = (const float*)d_in[15];
    const float* w1      = (const float*)d_in[16];
    const float* b1      = (const float*)d_in[17];
    const float* w2      = (const float*)d_in[18];
    const float* b2      = (const float*)d_in[19];
    float* out = (float*)d_out;

    float *hP, *qkvP, *ctxP, *aP, *hidP;
    cudaGetSymbolAddress((void**)&hP,   g_h);
    cudaGetSymbolAddress((void**)&qkvP, g_qkv);
    cudaGetSymbolAddress((void**)&ctxP, g_ctx);
    cudaGetSymbolAddress((void**)&aP,   g_a);
    cudaGetSymbolAddress((void**)&hidP, g_hid);

    const int M = TOK;

    // 1. h = LN1(x)
    ln_kernel<<<TOK / 8, 256>>>(x, n1g, n1b, hP);
    // 2. qkv = h @ d_qkv_w^T + b
    gemm_tc_kernel<0><<<dim3(768 / 128, M / 128), 256>>>(hP, d_qkv_w, d_qkv_b, nullptr, qkvP, M, 768, CCH);
    // 3. spatial shifted-window attention -> ctx
    spat_attn_kernel<<<2048, 256>>>(qkvP, d_tab, maskm, ctxP);
    // 4. a = ctx @ d_proj_w^T + b
    gemm_tc_kernel<0><<<dim3(CCH / 128, M / 128), 256>>>(ctxP, d_prj_w, d_prj_b, nullptr, aP, M, CCH, CCH);
    // 5. qkv = a @ p_qkv_w^T + b
    gemm_tc_kernel<0><<<dim3(768 / 128, M / 128), 256>>>(aP, p_qkv_w, p_qkv_b, nullptr, qkvP, M, 768, CCH);
    // 6. temporal attention -> ctx
    temp_attn_kernel<<<32768, 128>>>(qkvP, p_tab, ctxP);
    // 7. x1 = x + ctx @ p_proj_w^T + b     (written to d_out)
    gemm_tc_kernel<2><<<dim3(CCH / 128, M / 128), 256>>>(ctxP, p_prj_w, p_prj_b, x, out, M, CCH, CCH);
    // 8. y0 = LN2(x1)
    ln_kernel<<<TOK / 8, 256>>>(out, n2g, n2b, hP);
    // 9. hid = GELU(y0 @ w1^T + b1)
    gemm_tc_kernel<1><<<dim3(HID_N / 128, M / 128), 256>>>(hP, w1, b1, nullptr, hidP, M, HID_N, CCH);
    // 10. out = x1 + hid @ w2^T + b2   (in-place residual)
    gemm_tc_kernel<2><<<dim3(CCH / 128, M / 128), 256>>>(hidP, w2, b2, out, out, M, CCH, HID_N);
}

// round 4
// speedup vs baseline: 1.2146x; 1.2146x over previous
#include <cuda_runtime.h>
#include <cuda_bf16.h>
#include <math.h>
#include <stdint.h>

// Problem constants
#define TOK   131072        // B*D*H*W = 2*4*128*128
#define CCH   256
#define NH    8
#define HD    32
#define HID_N 1024

// ---------------------------------------------------------------------------
// Scratch buffers (__device__ globals — no allocations allowed)
// ---------------------------------------------------------------------------
__device__ float g_h  [TOK * CCH];     // LN output / reused
__device__ float g_qkv[TOK * 3 * CCH]; // qkv projections (reused for both attns)
__device__ float g_ctx[TOK * CCH];     // attention context (pre-proj)
__device__ float g_a  [TOK * CCH];     // spatial attention output
__device__ float g_hid[TOK * HID_N];   // MLP hidden

// ---------------------------------------------------------------------------
// LayerNorm: one warp per token (C=256)
// ---------------------------------------------------------------------------
__global__ void __launch_bounds__(256) ln_kernel(
    const float* __restrict__ x, const float* __restrict__ gamma,
    const float* __restrict__ beta, float* __restrict__ out)
{
    int warp = threadIdx.x >> 5, lane = threadIdx.x & 31;
    int token = blockIdx.x * 8 + warp;
    const float* xp = x + token * CCH;
    float4 x0 = *(const float4*)(xp + lane * 4);
    float4 x1 = *(const float4*)(xp + 128 + lane * 4);
    float s  = x0.x + x0.y + x0.z + x0.w + x1.x + x1.y + x1.z + x1.w;
    float s2 = x0.x*x0.x + x0.y*x0.y + x0.z*x0.z + x0.w*x0.w
             + x1.x*x1.x + x1.y*x1.y + x1.z*x1.z + x1.w*x1.w;
    #pragma unroll
    for (int o = 16; o > 0; o >>= 1) {
        s  += __shfl_xor_sync(0xffffffffu, s,  o);
        s2 += __shfl_xor_sync(0xffffffffu, s2, o);
    }
    float mu  = s * (1.0f / CCH);
    float var = s2 * (1.0f / CCH) - mu * mu;
    float rstd = rsqrtf(var + 1e-5f);
    float4 g0 = *(const float4*)(gamma + lane * 4);
    float4 g1 = *(const float4*)(gamma + 128 + lane * 4);
    float4 b0 = *(const float4*)(beta + lane * 4);
    float4 b1 = *(const float4*)(beta + 128 + lane * 4);
    float* op = out + token * CCH;
    float4 r0, r1;
    r0.x = (x0.x - mu) * rstd * g0.x + b0.x;
    r0.y = (x0.y - mu) * rstd * g0.y + b0.y;
    r0.z = (x0.z - mu) * rstd * g0.z + b0.z;
    r0.w = (x0.w - mu) * rstd * g0.w + b0.w;
    r1.x = (x1.x - mu) * rstd * g1.x + b1.x;
    r1.y = (x1.y - mu) * rstd * g1.y + b1.y;
    r1.z = (x1.z - mu) * rstd * g1.z + b1.z;
    r1.w = (x1.w - mu) * rstd * g1.w + b1.w;
    *(float4*)(op + lane * 4) = r0;
    *(float4*)(op + 128 + lane * 4) = r1;
}

// ---------------------------------------------------------------------------
// bf16 helpers
// ---------------------------------------------------------------------------
__device__ __forceinline__ uint32_t pack_bf16x2(float lo, float hi) {
    __nv_bfloat162 p = __float22bfloat162_rn(make_float2(lo, hi));
    return *(uint32_t*)&p;
}

#define MMA_BF16(d, a, b) \
    asm volatile( \
        "mma.sync.aligned.m16n8k16.row.col.f32.bf16.bf16.f32 " \
        "{%0,%1,%2,%3}, {%4,%5,%6,%7}, {%8,%9}, {%0,%1,%2,%3};\n" \
        : "+f"((d)[0]), "+f"((d)[1]), "+f"((d)[2]), "+f"((d)[3]) \
        : "r"((a)[0]), "r"((a)[1]), "r"((a)[2]), "r"((a)[3]), \
          "r"((b)[0]), "r"((b)[1]))

// ---------------------------------------------------------------------------
// bf16 tensor-core GEMM: out[M,N] = A[M,K] @ W[N,K]^T + bias, with epilogue
// EPI: 0 = bias, 1 = bias+GELU(exact), 2 = bias + aux residual add
// BM=BN=128, BK=32, 256 threads = 8 warps (2 along M x 4 along N),
// warp tile 64x32 = 4 m-tiles(16) x 4 n-tiles(8), mma.m16n8k16.bf16
// Smem holds k-pairs as bf16x2 (u32); row stride 20 u32 -> conflict-free frags.
// ---------------------------------------------------------------------------
template <int EPI>
__global__ void __launch_bounds__(256) gemm_tc_kernel(
    const float* __restrict__ A, const float* __restrict__ W,
    const float* __restrict__ bias, const float* __restrict__ aux,
    float* __restrict__ out, int M, int N, int K)
{
    constexpr int BM = 128, BN = 128, BK = 32;   // BK in k-elements
    constexpr int KP = BK / 2 + 4;               // 20 u32 per row (pad 4)
    __shared__ uint32_t As[BM][KP];
    __shared__ uint32_t Bs[BN][KP];

    const int tid  = threadIdx.x;
    const int wid  = tid >> 5, lane = tid & 31;
    const int g    = lane >> 2, tg = lane & 3;
    const int wm   = (wid & 1) * 64;        // warp row base in tile
    const int wn   = (wid >> 1) * 32;       // warp col base in tile
    const int bm   = blockIdx.y * BM, bn = blockIdx.x * BN;

    // global load mapping: 32 rows per pass, 8 float4 per row
    const int lr = tid >> 3;                // 0..31
    const int lc = (tid & 7) * 4;           // float col: 0,4,...,28
    const int lp = (tid & 7) * 2;           // pair col: 0,2,...,14
    const float* Ag = A + (size_t)(bm + lr) * K + lc;
    const float* Wg = W + (size_t)(bn + lr) * K + lc;

    float acc[4][4][4];
    #pragma unroll
    for (int mt = 0; mt < 4; mt++)
        #pragma unroll
        for (int nt = 0; nt < 4; nt++)
            #pragma unroll
            for (int c = 0; c < 4; c++) acc[mt][nt][c] = 0.0f;

    float4 pa[4], pb[4];
    #pragma unroll
    for (int i = 0; i < 4; i++) {
        pa[i] = *(const float4*)(Ag + (size_t)i * 32 * K);
        pb[i] = *(const float4*)(Wg + (size_t)i * 32 * K);
    }

    for (int k0 = 0; k0 < K; k0 += BK) {
        // stage current tiles into smem as bf16 pairs
        #pragma unroll
        for (int i = 0; i < 4; i++) {
            float4 a = pa[i], b = pb[i];
            As[lr + i * 32][lp    ] = pack_bf16x2(a.x, a.y);
            As[lr + i * 32][lp + 1] = pack_bf16x2(a.z, a.w);
            Bs[lr + i * 32][lp    ] = pack_bf16x2(b.x, b.y);
            Bs[lr + i * 32][lp + 1] = pack_bf16x2(b.z, b.w);
        }
        __syncthreads();

        // prefetch next tiles
        if (k0 + BK < K) {
            #pragma unroll
            for (int i = 0; i < 4; i++) {
                pa[i] = *(const float4*)(Ag + (size_t)i * 32 * K + k0 + BK);
                pb[i] = *(const float4*)(Wg + (size_t)i * 32 * K + k0 + BK);
            }
        }

        // compute: 2 k-steps of 16
        #pragma unroll
        for (int ks = 0; ks < 2; ks++) {
            uint32_t af[4][4], bf[4][2];
            #pragma unroll
            for (int mt = 0; mt < 4; mt++) {
                int r0 = wm + mt * 16 + g;
                af[mt][0] = As[r0    ][ks * 8 + tg];
                af[mt][1] = As[r0 + 8][ks * 8 + tg];
                af[mt][2] = As[r0    ][ks * 8 + tg + 4];
                af[mt][3] = As[r0 + 8][ks * 8 + tg + 4];
            }
            #pragma unroll
            for (int nt = 0; nt < 4; nt++) {
                int c0 = wn + nt * 8 + g;
                bf[nt][0] = Bs[c0][ks * 8 + tg];
                bf[nt][1] = Bs[c0][ks * 8 + tg + 4];
            }
            #pragma unroll
            for (int mt = 0; mt < 4; mt++)
                #pragma unroll
                for (int nt = 0; nt < 4; nt++)
                    MMA_BF16(acc[mt][nt], af[mt], bf[nt]);
        }
        __syncthreads();
    }

    // epilogue (fp32)
    #pragma unroll
    for (int mt = 0; mt < 4; mt++) {
        int row0 = bm + wm + mt * 16 + g;
        #pragma unroll
        for (int nt = 0; nt < 4; nt++) {
            int col = bn + wn + nt * 8 + tg * 2;
            float bv0 = bias[col], bv1 = bias[col + 1];
            float v00 = acc[mt][nt][0] + bv0, v01 = acc[mt][nt][1] + bv1;
            float v10 = acc[mt][nt][2] + bv0, v11 = acc[mt][nt][3] + bv1;
            if (EPI == 1) {
                v00 = 0.5f * v00 * (1.0f + erff(v00 * 0.70710678118654752f));
                v01 = 0.5f * v01 * (1.0f + erff(v01 * 0.70710678118654752f));
                v10 = 0.5f * v10 * (1.0f + erff(v10 * 0.70710678118654752f));
                v11 = 0.5f * v11 * (1.0f + erff(v11 * 0.70710678118654752f));
            }
            if (EPI == 2) {
                float2 a0 = *(const float2*)(aux + (size_t)row0 * N + col);
                float2 a1 = *(const float2*)(aux + (size_t)(row0 + 8) * N + col);
                v00 += a0.x; v01 += a0.y; v10 += a1.x; v11 += a1.y;
            }
            float2 r0 = { v00, v01 }, r1 = { v10, v11 };
            *(float2*)(out + (size_t)row0 * N + col) = r0;
            *(float2*)(out + (size_t)(row0 + 8) * N + col) = r1;
        }
    }
}

// ---------------------------------------------------------------------------
// Spatial shifted-window attention (window 1x8x8, N=64, shift (0,4,4))
// One block per window (2048 blocks), looping over 8 heads.
// ---------------------------------------------------------------------------
__global__ void __launch_bounds__(256) spat_attn_kernel(
    const float* __restrict__ qkv, const float* __restrict__ table,
    const float* __restrict__ mask, float* __restrict__ ctx)
{
    __shared__ float qs[64][33], ks[64][33], vs[64][33];
    __shared__ float ss[64][65];
    __shared__ int tix[64];
    const int tid = threadIdx.x;
    const int bw = blockIdx.x;
    const int b = bw >> 10, wi = bw & 1023;          // wi = (dwin*16+hwin)*16+wwin
    const int dwin = wi >> 8, hwin = (wi >> 4) & 15, wwin = wi & 15;
    const float rsc = 0.17677669529663687f;          // 1/sqrt(32)

    if (tid < 64) {
        int yy = tid >> 3, xx = tid & 7;
        int h = hwin * 8 + yy, w = wwin * 8 + xx;
        int ho = (h + 4) & 127, wo = (w + 4) & 127;   // undo roll(-shift)
        tix[tid] = ((b * 4 + dwin) * 128 + ho) * 128 + wo;
    }
    __syncthreads();
    const float* maskw = mask + wi * 4096;

    for (int head = 0; head < NH; head++) {
        for (int idx = tid; idx < 2048; idx += 256) {
            int r = idx >> 5, c = idx & 31;
            const float* base = qkv + (size_t)tix[r] * 768 + head * HD + c;
            qs[r][c] = base[0] * rsc;
            ks[r][c] = base[256];
            vs[r][c] = base[512];
        }
        __syncthreads();
        for (int idx = tid; idx < 4096; idx += 256) {
            int i = idx >> 6, j = idx & 63;
            float s = 0.0f;
            #pragma unroll
            for (int c = 0; c < 32; c++) s += qs[i][c] * ks[j][c];
            int yi = i >> 3, xi = i & 7, yj = j >> 3, xj = j & 7;
            int rp = (yi - yj + 7) * 15 + (xi - xj + 7);
            s += table[rp * NH + head] + maskw[idx];
            ss[i][j] = s;
        }
        __syncthreads();
        {   // softmax, 4 threads per row
            int r = tid >> 2, part = tid & 3;
            float m = -1e30f;
            #pragma unroll
            for (int j = 0; j < 16; j++) m = fmaxf(m, ss[r][part * 16 + j]);
            m = fmaxf(m, __shfl_xor_sync(0xffffffffu, m, 1));
            m = fmaxf(m, __shfl_xor_sync(0xffffffffu, m, 2));
            float sum = 0.0f;
            #pragma unroll
            for (int j = 0; j < 16; j++) {
                float e = __expf(ss[r][part * 16 + j] - m);
                ss[r][part * 16 + j] = e;
                sum += e;
            }
            sum += __shfl_xor_sync(0xffffffffu, sum, 1);
            sum += __shfl_xor_sync(0xffffffffu, sum, 2);
            float inv = 1.0f / sum;
            #pragma unroll
            for (int j = 0; j < 16; j++) ss[r][part * 16 + j] *= inv;
        }
        __syncthreads();
        for (int idx = tid; idx < 2048; idx += 256) {
            int i = idx >> 5, c = idx & 31;
            float o = 0.0f;
            #pragma unroll
            for (int j = 0; j < 64; j++) o += ss[i][j] * vs[j][c];
            ctx[(size_t)tix[i] * CCH + head * HD + c] = o;
        }
        __syncthreads();
    }
}

// ---------------------------------------------------------------------------
// Temporal point attention (window 4x1x1, N=4). One block per (b,h,w).
// ---------------------------------------------------------------------------
__global__ void __launch_bounds__(128) temp_attn_kernel(
    const float* __restrict__ qkv, const float* __restrict__ table,
    float* __restrict__ ctx)
{
    __shared__ float qs[4][256], ks[4][256], vs[4][256];
    __shared__ float ps[NH][4][4];
    const int tid = threadIdx.x;
    const int wt = blockIdx.x;
    const int b = wt >> 14, hw = wt & 16383;
    const int base0 = b * 4 * 16384 + hw;   // token index of depth 0

    for (int idx = tid; idx < 1024; idx += 128) {
        int d = idx >> 8, c = idx & 255;
        const float* p = qkv + (size_t)(base0 + d * 16384) * 768 + c;
        qs[d][c] = p[0] * 0.17677669529663687f;
        ks[d][c] = p[256];
        vs[d][c] = p[512];
    }
    __syncthreads();
    {
        int head = tid >> 4, i = (tid >> 2) & 3, j = tid & 3;
        float s = 0.0f;
        #pragma unroll
        for (int c = 0; c < 32; c++) s += qs[i][head * HD + c] * ks[j][head * HD + c];
        s += table[(i - j + 3) * NH + head];
        ps[head][i][j] = s;
    }
    __syncthreads();
    if (tid < 32) {
        int head = tid >> 2, i = tid & 3;
        float a0 = ps[head][i][0], a1 = ps[head][i][1];
        float a2 = ps[head][i][2], a3 = ps[head][i][3];
        float m = fmaxf(fmaxf(a0, a1), fmaxf(a2, a3));
        float e0 = __expf(a0 - m), e1 = __expf(a1 - m);
        float e2 = __expf(a2 - m), e3 = __expf(a3 - m);
        float inv = 1.0f / (e0 + e1 + e2 + e3);
        ps[head][i][0] = e0 * inv; ps[head][i][1] = e1 * inv;
        ps[head][i][2] = e2 * inv; ps[head][i][3] = e3 * inv;
    }
    __syncthreads();
    for (int idx = tid; idx < 1024; idx += 128) {
        int i = idx >> 8, c = idx & 255;
        int head = c >> 5;
        float o = ps[head][i][0] * vs[0][c] + ps[head][i][1] * vs[1][c]
                + ps[head][i][2] * vs[2][c] + ps[head][i][3] * vs[3][c];
        ctx[(size_t)(base0 + i * 16384) * CCH + c] = o;
    }
}

// ---------------------------------------------------------------------------
// Host launch
// ---------------------------------------------------------------------------
extern "C" void kernel_launch(void* const* d_in, const int* in_sizes, int n_in,
                              void* d_out, int out_size)
{
    const float* x       = (const float*)d_in[0];
    const float* maskm   = (const float*)d_in[1];
    const float* n1g     = (const float*)d_in[2];
    const float* n1b     = (const float*)d_in[3];
    const float* d_qkv_w = (const float*)d_in[4];
    const float* d_qkv_b = (const float*)d_in[5];
    const float* d_prj_w = (const float*)d_in[6];
    const float* d_prj_b = (const float*)d_in[7];
    const float* d_tab   = (const float*)d_in[8];
    const float* p_qkv_w = (const float*)d_in[9];
    const float* p_qkv_b = (const float*)d_in[10];
    const float* p_prj_w = (const float*)d_in[11];
    const float* p_prj_b = (const float*)d_in[12];
    const float* p_tab   = (const float*)d_in[13];
    const float* n2g     = (const float*)d_in[14];
    const float* n2b     = (const float*)d_in[15];
    const float* w1      = (const float*)d_in[16];
    const float* b1      = (const float*)d_in[17];
    const float* w2      = (const float*)d_in[18];
    const float* b2      = (const float*)d_in[19];
    float* out = (float*)d_out;

    float *hP, *qkvP, *ctxP, *aP, *hidP;
    cudaGetSymbolAddress((void**)&hP,   g_h);
    cudaGetSymbolAddress((void**)&qkvP, g_qkv);
    cudaGetSymbolAddress((void**)&ctxP, g_ctx);
    cudaGetSymbolAddress((void**)&aP,   g_a);
    cudaGetSymbolAddress((void**)&hidP, g_hid);

    const int M = TOK;

    // 1. h = LN1(x)
    ln_kernel<<<TOK / 8, 256>>>(x, n1g, n1b, hP);
    // 2. qkv = h @ d_qkv_w^T + b
    gemm_tc_kernel<0><<<dim3(768 / 128, M / 128), 256>>>(hP, d_qkv_w, d_qkv_b, nullptr, qkvP, M, 768, CCH);
    // 3. spatial shifted-window attention -> ctx
    spat_attn_kernel<<<2048, 256>>>(qkvP, d_tab, maskm, ctxP);
    // 4. a = ctx @ d_proj_w^T + b
    gemm_tc_kernel<0><<<dim3(CCH / 128, M / 128), 256>>>(ctxP, d_prj_w, d_prj_b, nullptr, aP, M, CCH, CCH);
    // 5. qkv = a @ p_qkv_w^T + b
    gemm_tc_kernel<0><<<dim3(768 / 128, M / 128), 256>>>(aP, p_qkv_w, p_qkv_b, nullptr, qkvP, M, 768, CCH);
    // 6. temporal attention -> ctx
    temp_attn_kernel<<<32768, 128>>>(qkvP, p_tab, ctxP);
    // 7. x1 = x + ctx @ p_proj_w^T + b     (written to d_out)
    gemm_tc_kernel<2><<<dim3(CCH / 128, M / 128), 256>>>(ctxP, p_prj_w, p_prj_b, x, out, M, CCH, CCH);
    // 8. y0 = LN2(x1)
    ln_kernel<<<TOK / 8, 256>>>(out, n2g, n2b, hP);
    // 9. hid = GELU(y0 @ w1^T + b1)
    gemm_tc_kernel<1><<<dim3(HID_N / 128, M / 128), 256>>>(hP, w1, b1, nullptr, hidP, M, HID_N, CCH);
    // 10. out = x1 + hid @ w2^T + b2   (in-place residual)
    gemm_tc_kernel<2><<<dim3(CCH / 128, M / 128), 256>>>(hidP, w2, b2, out, out, M, CCH, HID_N);
}

// round 5
// speedup vs baseline: 1.2575x; 1.0353x over previous
#include <cuda_runtime.h>
#include <cuda_bf16.h>
#include <math.h>
#include <stdint.h>

// Problem constants
#define TOK   131072        // B*D*H*W = 2*4*128*128
#define CCH   256
#define NH    8
#define HD    32
#define HID_N 1024

// ---------------------------------------------------------------------------
// Scratch buffers (__device__ globals — no allocations allowed)
// ---------------------------------------------------------------------------
__device__ float g_h  [TOK * CCH];     // LN output / reused
__device__ float g_qkv[TOK * 3 * CCH]; // qkv projections (reused for both attns)
__device__ float g_ctx[TOK * CCH];     // attention context (pre-proj)
__device__ float g_a  [TOK * CCH];     // spatial attention output
__device__ float g_hid[TOK * HID_N];   // MLP hidden

// ---------------------------------------------------------------------------
// LayerNorm: one warp per token (C=256)
// ---------------------------------------------------------------------------
__global__ void __launch_bounds__(256) ln_kernel(
    const float* __restrict__ x, const float* __restrict__ gamma,
    const float* __restrict__ beta, float* __restrict__ out)
{
    int warp = threadIdx.x >> 5, lane = threadIdx.x & 31;
    int token = blockIdx.x * 8 + warp;
    const float* xp = x + token * CCH;
    float4 x0 = *(const float4*)(xp + lane * 4);
    float4 x1 = *(const float4*)(xp + 128 + lane * 4);
    float s  = x0.x + x0.y + x0.z + x0.w + x1.x + x1.y + x1.z + x1.w;
    float s2 = x0.x*x0.x + x0.y*x0.y + x0.z*x0.z + x0.w*x0.w
             + x1.x*x1.x + x1.y*x1.y + x1.z*x1.z + x1.w*x1.w;
    #pragma unroll
    for (int o = 16; o > 0; o >>= 1) {
        s  += __shfl_xor_sync(0xffffffffu, s,  o);
        s2 += __shfl_xor_sync(0xffffffffu, s2, o);
    }
    float mu  = s * (1.0f / CCH);
    float var = s2 * (1.0f / CCH) - mu * mu;
    float rstd = rsqrtf(var + 1e-5f);
    float4 g0 = *(const float4*)(gamma + lane * 4);
    float4 g1 = *(const float4*)(gamma + 128 + lane * 4);
    float4 b0 = *(const float4*)(beta + lane * 4);
    float4 b1 = *(const float4*)(beta + 128 + lane * 4);
    float* op = out + token * CCH;
    float4 r0, r1;
    r0.x = (x0.x - mu) * rstd * g0.x + b0.x;
    r0.y = (x0.y - mu) * rstd * g0.y + b0.y;
    r0.z = (x0.z - mu) * rstd * g0.z + b0.z;
    r0.w = (x0.w - mu) * rstd * g0.w + b0.w;
    r1.x = (x1.x - mu) * rstd * g1.x + b1.x;
    r1.y = (x1.y - mu) * rstd * g1.y + b1.y;
    r1.z = (x1.z - mu) * rstd * g1.z + b1.z;
    r1.w = (x1.w - mu) * rstd * g1.w + b1.w;
    *(float4*)(op + lane * 4) = r0;
    *(float4*)(op + 128 + lane * 4) = r1;
}

// ---------------------------------------------------------------------------
// bf16 helpers
// ---------------------------------------------------------------------------
__device__ __forceinline__ uint32_t pack_bf16x2(float lo, float hi) {
    __nv_bfloat162 p = __float22bfloat162_rn(make_float2(lo, hi));
    return *(uint32_t*)&p;
}

#define MMA_BF16(d, a, b) \
    asm volatile( \
        "mma.sync.aligned.m16n8k16.row.col.f32.bf16.bf16.f32 " \
        "{%0,%1,%2,%3}, {%4,%5,%6,%7}, {%8,%9}, {%0,%1,%2,%3};\n" \
        : "+f"((d)[0]), "+f"((d)[1]), "+f"((d)[2]), "+f"((d)[3]) \
        : "r"((a)[0]), "r"((a)[1]), "r"((a)[2]), "r"((a)[3]), \
          "r"((b)[0]), "r"((b)[1]))

__device__ __forceinline__ void ldsm_x4(uint32_t& r0, uint32_t& r1,
                                        uint32_t& r2, uint32_t& r3, uint32_t addr) {
    asm volatile("ldmatrix.sync.aligned.m8n8.x4.shared.b16 {%0,%1,%2,%3}, [%4];"
        : "=r"(r0), "=r"(r1), "=r"(r2), "=r"(r3) : "r"(addr));
}

// ---------------------------------------------------------------------------
// bf16 tensor-core GEMM: out[M,N] = A[M,K] @ W[N,K]^T + bias, with epilogue
// EPI: 0 = bias, 1 = bias+GELU(exact), 2 = bias + aux residual add
// BM=BN=128, BK=32, 256 threads = 8 warps (2 along M x 4 along N),
// warp tile 64x32, mma.m16n8k16.bf16, fragment loads via ldmatrix.x4.
// Smem rows: 20 u32 (80B, multiple of 16 -> LDSM-aligned, conflict-free).
// ---------------------------------------------------------------------------
template <int EPI>
__global__ void __launch_bounds__(256) gemm_tc_kernel(
    const float* __restrict__ A, const float* __restrict__ W,
    const float* __restrict__ bias, const float* __restrict__ aux,
    float* __restrict__ out, int M, int N, int K)
{
    constexpr int BM = 128, BN = 128, BK = 32;   // BK in k-elements
    constexpr int KP = BK / 2 + 4;               // 20 u32 per row (pad 4)
    __shared__ uint32_t As[BM][KP];
    __shared__ uint32_t Bs[BN][KP];

    const int tid  = threadIdx.x;
    const int wid  = tid >> 5, lane = tid & 31;
    const int g    = lane >> 2, tg = lane & 3;
    const int wm   = (wid & 1) * 64;        // warp row base in tile
    const int wn   = (wid >> 1) * 32;       // warp col base in tile
    const int bm   = blockIdx.y * BM, bn = blockIdx.x * BN;

    // global load mapping: 32 rows per pass, 8 float4 per row
    const int lr = tid >> 3;                // 0..31
    const int lc = (tid & 7) * 4;           // float col: 0,4,...,28
    const int lp = (tid & 7) * 2;           // pair col: 0,2,...,14
    const float* Ag = A + (size_t)(bm + lr) * K + lc;
    const float* Wg = W + (size_t)(bn + lr) * K + lc;

    // ldmatrix per-lane base addresses
    const uint32_t sA = (uint32_t)__cvta_generic_to_shared(&As[0][0]);
    const uint32_t sB = (uint32_t)__cvta_generic_to_shared(&Bs[0][0]);
    const int l8 = lane & 7, grp = lane >> 3;
    // A: groups -> {(row+0,klo),(row+8,klo),(row+0,khi),(row+8,khi)}
    const uint32_t aBase = sA + (uint32_t)((wm + (grp & 1) * 8 + l8) * (KP * 4) + (grp >> 1) * 16);
    // B: groups -> {(n+0,klo),(n+0,khi),(n+8,klo),(n+8,khi)}  (two n-tiles per x4)
    const uint32_t bBase = sB + (uint32_t)((wn + (grp >> 1) * 8 + l8) * (KP * 4) + (grp & 1) * 16);

    float acc[4][4][4];
    #pragma unroll
    for (int mt = 0; mt < 4; mt++)
        #pragma unroll
        for (int nt = 0; nt < 4; nt++)
            #pragma unroll
            for (int c = 0; c < 4; c++) acc[mt][nt][c] = 0.0f;

    float4 pa[4], pb[4];
    #pragma unroll
    for (int i = 0; i < 4; i++) {
        pa[i] = *(const float4*)(Ag + (size_t)i * 32 * K);
        pb[i] = *(const float4*)(Wg + (size_t)i * 32 * K);
    }

    for (int k0 = 0; k0 < K; k0 += BK) {
        // stage current tiles into smem as bf16 pairs (vectorized 8B stores)
        #pragma unroll
        for (int i = 0; i < 4; i++) {
            float4 a = pa[i], b = pb[i];
            uint2 au = { pack_bf16x2(a.x, a.y), pack_bf16x2(a.z, a.w) };
            uint2 bu = { pack_bf16x2(b.x, b.y), pack_bf16x2(b.z, b.w) };
            *(uint2*)&As[lr + i * 32][lp] = au;
            *(uint2*)&Bs[lr + i * 32][lp] = bu;
        }
        __syncthreads();

        // prefetch next tiles
        if (k0 + BK < K) {
            #pragma unroll
            for (int i = 0; i < 4; i++) {
                pa[i] = *(const float4*)(Ag + (size_t)i * 32 * K + k0 + BK);
                pb[i] = *(const float4*)(Wg + (size_t)i * 32 * K + k0 + BK);
            }
        }

        // compute: 2 k-steps of 16, fragments via ldmatrix
        #pragma unroll
        for (int ks = 0; ks < 2; ks++) {
            uint32_t af[4][4], bf[4][2];
            #pragma unroll
            for (int mt = 0; mt < 4; mt++)
                ldsm_x4(af[mt][0], af[mt][1], af[mt][2], af[mt][3],
                        aBase + (uint32_t)(mt * 16 * (KP * 4) + ks * 32));
            #pragma unroll
            for (int np = 0; np < 2; np++)
                ldsm_x4(bf[np * 2][0], bf[np * 2][1], bf[np * 2 + 1][0], bf[np * 2 + 1][1],
                        bBase + (uint32_t)(np * 16 * (KP * 4) + ks * 32));
            #pragma unroll
            for (int mt = 0; mt < 4; mt++)
                #pragma unroll
                for (int nt = 0; nt < 4; nt++)
                    MMA_BF16(acc[mt][nt], af[mt], bf[nt]);
        }
        __syncthreads();
    }

    // epilogue (fp32)
    #pragma unroll
    for (int mt = 0; mt < 4; mt++) {
        int row0 = bm + wm + mt * 16 + g;
        #pragma unroll
        for (int nt = 0; nt < 4; nt++) {
            int col = bn + wn + nt * 8 + tg * 2;
            float bv0 = bias[col], bv1 = bias[col + 1];
            float v00 = acc[mt][nt][0] + bv0, v01 = acc[mt][nt][1] + bv1;
            float v10 = acc[mt][nt][2] + bv0, v11 = acc[mt][nt][3] + bv1;
            if (EPI == 1) {
                v00 = 0.5f * v00 * (1.0f + erff(v00 * 0.70710678118654752f));
                v01 = 0.5f * v01 * (1.0f + erff(v01 * 0.70710678118654752f));
                v10 = 0.5f * v10 * (1.0f + erff(v10 * 0.70710678118654752f));
                v11 = 0.5f * v11 * (1.0f + erff(v11 * 0.70710678118654752f));
            }
            if (EPI == 2) {
                float2 a0 = *(const float2*)(aux + (size_t)row0 * N + col);
                float2 a1 = *(const float2*)(aux + (size_t)(row0 + 8) * N + col);
                v00 += a0.x; v01 += a0.y; v10 += a1.x; v11 += a1.y;
            }
            float2 r0 = { v00, v01 }, r1 = { v10, v11 };
            *(float2*)(out + (size_t)row0 * N + col) = r0;
            *(float2*)(out + (size_t)(row0 + 8) * N + col) = r1;
        }
    }
}

// ---------------------------------------------------------------------------
// Spatial shifted-window attention (window 1x8x8, N=64, shift (0,4,4))
// One block per window (2048 blocks), looping over 8 heads.
// ---------------------------------------------------------------------------
__global__ void __launch_bounds__(256) spat_attn_kernel(
    const float* __restrict__ qkv, const float* __restrict__ table,
    const float* __restrict__ mask, float* __restrict__ ctx)
{
    __shared__ float qs[64][33], ks[64][33], vs[64][33];
    __shared__ float ss[64][65];
    __shared__ int tix[64];
    const int tid = threadIdx.x;
    const int bw = blockIdx.x;
    const int b = bw >> 10, wi = bw & 1023;          // wi = (dwin*16+hwin)*16+wwin
    const int dwin = wi >> 8, hwin = (wi >> 4) & 15, wwin = wi & 15;
    const float rsc = 0.17677669529663687f;          // 1/sqrt(32)

    if (tid < 64) {
        int yy = tid >> 3, xx = tid & 7;
        int h = hwin * 8 + yy, w = wwin * 8 + xx;
        int ho = (h + 4) & 127, wo = (w + 4) & 127;   // undo roll(-shift)
        tix[tid] = ((b * 4 + dwin) * 128 + ho) * 128 + wo;
    }
    __syncthreads();
    const float* maskw = mask + wi * 4096;

    for (int head = 0; head < NH; head++) {
        for (int idx = tid; idx < 2048; idx += 256) {
            int r = idx >> 5, c = idx & 31;
            const float* base = qkv + (size_t)tix[r] * 768 + head * HD + c;
            qs[r][c] = base[0] * rsc;
            ks[r][c] = base[256];
            vs[r][c] = base[512];
        }
        __syncthreads();
        for (int idx = tid; idx < 4096; idx += 256) {
            int i = idx >> 6, j = idx & 63;
            float s = 0.0f;
            #pragma unroll
            for (int c = 0; c < 32; c++) s += qs[i][c] * ks[j][c];
            int yi = i >> 3, xi = i & 7, yj = j >> 3, xj = j & 7;
            int rp = (yi - yj + 7) * 15 + (xi - xj + 7);
            s += table[rp * NH + head] + maskw[idx];
            ss[i][j] = s;
        }
        __syncthreads();
        {   // softmax, 4 threads per row
            int r = tid >> 2, part = tid & 3;
            float m = -1e30f;
            #pragma unroll
            for (int j = 0; j < 16; j++) m = fmaxf(m, ss[r][part * 16 + j]);
            m = fmaxf(m, __shfl_xor_sync(0xffffffffu, m, 1));
            m = fmaxf(m, __shfl_xor_sync(0xffffffffu, m, 2));
            float sum = 0.0f;
            #pragma unroll
            for (int j = 0; j < 16; j++) {
                float e = __expf(ss[r][part * 16 + j] - m);
                ss[r][part * 16 + j] = e;
                sum += e;
            }
            sum += __shfl_xor_sync(0xffffffffu, sum, 1);
            sum += __shfl_xor_sync(0xffffffffu, sum, 2);
            float inv = 1.0f / sum;
            #pragma unroll
            for (int j = 0; j < 16; j++) ss[r][part * 16 + j] *= inv;
        }
        __syncthreads();
        for (int idx = tid; idx < 2048; idx += 256) {
            int i = idx >> 5, c = idx & 31;
            float o = 0.0f;
            #pragma unroll
            for (int j = 0; j < 64; j++) o += ss[i][j] * vs[j][c];
            ctx[(size_t)tix[i] * CCH + head * HD + c] = o;
        }
        __syncthreads();
    }
}

// ---------------------------------------------------------------------------
// Temporal point attention (window 4x1x1, N=4). One block per (b,h,w).
// ---------------------------------------------------------------------------
__global__ void __launch_bounds__(128) temp_attn_kernel(
    const float* __restrict__ qkv, const float* __restrict__ table,
    float* __restrict__ ctx)
{
    __shared__ float qs[4][256], ks[4][256], vs[4][256];
    __shared__ float ps[NH][4][4];
    const int tid = threadIdx.x;
    const int wt = blockIdx.x;
    const int b = wt >> 14, hw = wt & 16383;
    const int base0 = b * 4 * 16384 + hw;   // token index of depth 0

    for (int idx = tid; idx < 1024; idx += 128) {
        int d = idx >> 8, c = idx & 255;
        const float* p = qkv + (size_t)(base0 + d * 16384) * 768 + c;
        qs[d][c] = p[0] * 0.17677669529663687f;
        ks[d][c] = p[256];
        vs[d][c] = p[512];
    }
    __syncthreads();
    {
        int head = tid >> 4, i = (tid >> 2) & 3, j = tid & 3;
        float s = 0.0f;
        #pragma unroll
        for (int c = 0; c < 32; c++) s += qs[i][head * HD + c] * ks[j][head * HD + c];
        s += table[(i - j + 3) * NH + head];
        ps[head][i][j] = s;
    }
    __syncthreads();
    if (tid < 32) {
        int head = tid >> 2, i = tid & 3;
        float a0 = ps[head][i][0], a1 = ps[head][i][1];
        float a2 = ps[head][i][2], a3 = ps[head][i][3];
        float m = fmaxf(fmaxf(a0, a1), fmaxf(a2, a3));
        float e0 = __expf(a0 - m), e1 = __expf(a1 - m);
        float e2 = __expf(a2 - m), e3 = __expf(a3 - m);
        float inv = 1.0f / (e0 + e1 + e2 + e3);
        ps[head][i][0] = e0 * inv; ps[head][i][1] = e1 * inv;
        ps[head][i][2] = e2 * inv; ps[head][i][3] = e3 * inv;
    }
    __syncthreads();
    for (int idx = tid; idx < 1024; idx += 128) {
        int i = idx >> 8, c = idx & 255;
        int head = c >> 5;
        float o = ps[head][i][0] * vs[0][c] + ps[head][i][1] * vs[1][c]
                + ps[head][i][2] * vs[2][c] + ps[head][i][3] * vs[3][c];
        ctx[(size_t)(base0 + i * 16384) * CCH + c] = o;
    }
}

// ---------------------------------------------------------------------------
// Host launch
// ---------------------------------------------------------------------------
extern "C" void kernel_launch(void* const* d_in, const int* in_sizes, int n_in,
                              void* d_out, int out_size)
{
    const float* x       = (const float*)d_in[0];
    const float* maskm   = (const float*)d_in[1];
    const float* n1g     = (const float*)d_in[2];
    const float* n1b     = (const float*)d_in[3];
    const float* d_qkv_w = (const float*)d_in[4];
    const float* d_qkv_b = (const float*)d_in[5];
    const float* d_prj_w = (const float*)d_in[6];
    const float* d_prj_b = (const float*)d_in[7];
    const float* d_tab   = (const float*)d_in[8];
    const float* p_qkv_w = (const float*)d_in[9];
    const float* p_qkv_b = (const float*)d_in[10];
    const float* p_prj_w = (const float*)d_in[11];
    const float* p_prj_b = (const float*)d_in[12];
    const float* p_tab   = (const float*)d_in[13];
    const float* n2g     = (const float*)d_in[14];
    const float* n2b     = (const float*)d_in[15];
    const float* w1      = (const float*)d_in[16];
    const float* b1      = (const float*)d_in[17];
    const float* w2      = (const float*)d_in[18];
    const float* b2      = (const float*)d_in[19];
    float* out = (float*)d_out;

    float *hP, *qkvP, *ctxP, *aP, *hidP;
    cudaGetSymbolAddress((void**)&hP,   g_h);
    cudaGetSymbolAddress((void**)&qkvP, g_qkv);
    cudaGetSymbolAddress((void**)&ctxP, g_ctx);
    cudaGetSymbolAddress((void**)&aP,   g_a);
    cudaGetSymbolAddress((void**)&hidP, g_hid);

    const int M = TOK;

    // 1. h = LN1(x)
    ln_kernel<<<TOK / 8, 256>>>(x, n1g, n1b, hP);
    // 2. qkv = h @ d_qkv_w^T + b
    gemm_tc_kernel<0><<<dim3(768 / 128, M / 128), 256>>>(hP, d_qkv_w, d_qkv_b, nullptr, qkvP, M, 768, CCH);
    // 3. spatial shifted-window attention -> ctx
    spat_attn_kernel<<<2048, 256>>>(qkvP, d_tab, maskm, ctxP);
    // 4. a = ctx @ d_proj_w^T + b
    gemm_tc_kernel<0><<<dim3(CCH / 128, M / 128), 256>>>(ctxP, d_prj_w, d_prj_b, nullptr, aP, M, CCH, CCH);
    // 5. qkv = a @ p_qkv_w^T + b
    gemm_tc_kernel<0><<<dim3(768 / 128, M / 128), 256>>>(aP, p_qkv_w, p_qkv_b, nullptr, qkvP, M, 768, CCH);
    // 6. temporal attention -> ctx
    temp_attn_kernel<<<32768, 128>>>(qkvP, p_tab, ctxP);
    // 7. x1 = x + ctx @ p_proj_w^T + b     (written to d_out)
    gemm_tc_kernel<2><<<dim3(CCH / 128, M / 128), 256>>>(ctxP, p_prj_w, p_prj_b, x, out, M, CCH, CCH);
    // 8. y0 = LN2(x1)
    ln_kernel<<<TOK / 8, 256>>>(out, n2g, n2b, hP);
    // 9. hid = GELU(y0 @ w1^T + b1)
    gemm_tc_kernel<1><<<dim3(HID_N / 128, M / 128), 256>>>(hP, w1, b1, nullptr, hidP, M, HID_N, CCH);
    // 10. out = x1 + hid @ w2^T + b2   (in-place residual)
    gemm_tc_kernel<2><<<dim3(CCH / 128, M / 128), 256>>>(hidP, w2, b2, out, out, M, CCH, HID_N);
}